// round 3
// baseline (speedup 1.0000x reference)
#include <cuda_runtime.h>

#define FULL 0xFFFFFFFFu

// Problem shape (fixed): N=1, L=S=512, H=8, D=M=32
constexpr int L = 512;
constexpr int H = 8;
constexpr int NCHUNK = 16;            // 16 chunks x 32 rows
constexpr int NBLOCKS = NCHUNK * H;   // 128 blocks, <= 148 SMs -> co-resident
constexpr int MATS = 3 * 1024 + 32;   // KK(1024) SQQ(1024) KV(1024) Ksum(32)
constexpr float K_SCALE = 0.05892556509887896f; // 1/(3*sqrt(32))

__device__ float g_part[NBLOCKS * MATS];
__device__ float g_mats[H * MATS];
__device__ unsigned g_cnt = 0;
__device__ unsigned g_gen = 0;

__device__ __forceinline__ unsigned ld_acq(const unsigned* p) {
    unsigned v;
    asm volatile("ld.acquire.gpu.u32 %0, [%1];" : "=r"(v) : "l"(p) : "memory");
    return v;
}
__device__ __forceinline__ void red_add_rel(unsigned* p, unsigned v) {
    asm volatile("red.release.gpu.add.u32 [%0], %1;" :: "l"(p), "r"(v) : "memory");
}
__device__ __forceinline__ unsigned atom_add_acqrel(unsigned* p, unsigned v) {
    unsigned old;
    asm volatile("atom.acq_rel.gpu.add.u32 %0, [%1], %2;"
                 : "=r"(old) : "l"(p), "r"(v) : "memory");
    return old;
}

// Software grid barrier (sense-reversal). Safe: all 128 CTAs are wave-1
// co-resident (grid < #SMs at this smem/reg footprint). Replay-safe: g_gen
// increases monotonically across graph replays; g_cnt self-resets.
__device__ __forceinline__ void grid_barrier() {
    __syncthreads();
    if (threadIdx.x == 0) {
        unsigned my = ld_acq(&g_gen);
        if (atom_add_acqrel(&g_cnt, 1u) == NBLOCKS - 1) {
            g_cnt = 0;                  // only owner writes; next use ordered by release below
            red_add_rel(&g_gen, 1u);
        } else {
            while (ld_acq(&g_gen) == my) { __nanosleep(40); }
        }
    }
    __syncthreads();
}

__global__ __launch_bounds__(256) void fused_kernel(
        const float* __restrict__ q, const float* __restrict__ k,
        const float* __restrict__ v, const float* __restrict__ klen,
        float* __restrict__ out) {
    __shared__ __align__(16) float sQ[32][36];
    __shared__ __align__(16) float sK[32][36];
    __shared__ __align__(16) float sV[32][36];
    __shared__ float sKK[32][33];
    __shared__ float sQQ[32][33];
    __shared__ float sKV[32][33];   // KV[d][m] = sum_s K[s][d] V[s][m]
    __shared__ float sKs[32];

    int bx = blockIdx.x;
    int h = bx & 7, c = bx >> 3;          // head, 32-row chunk
    int tid = threadIdx.x, lane = tid & 31, w = tid >> 5;

    // ---- Phase 1a: load raw tiles (coalesced) ----
    for (int i = tid; i < 1024; i += 256) {
        int r = i >> 5, col = i & 31;
        int g = ((c * 32 + r) * H + h) * 32 + col;
        sQ[r][col] = q[g];
        sK[r][col] = k[g];
        sV[r][col] = v[g];
    }
    __syncthreads();

    // ---- Phase 1b: LayerNorm in-block (warp w -> rows w, w+8, w+16, w+24) ----
    #pragma unroll
    for (int rr = 0; rr < 4; rr++) {
        int r = w + rr * 8;
        float x = sQ[r][lane], y = sK[r][lane];
        float sx = x, sxx = x * x, sy = y, syy = y * y;
        #pragma unroll
        for (int o = 16; o; o >>= 1) {
            sx  += __shfl_xor_sync(FULL, sx,  o);
            sxx += __shfl_xor_sync(FULL, sxx, o);
            sy  += __shfl_xor_sync(FULL, sy,  o);
            syy += __shfl_xor_sync(FULL, syy, o);
        }
        float muq = sx * (1.0f / 32.0f);
        float vq  = fmaf(-muq, muq, sxx * (1.0f / 32.0f));
        sQ[r][lane] = (x - muq) * rsqrtf(vq + 1e-5f);
        float muk = sy * (1.0f / 32.0f);
        float vk  = fmaf(-muk, muk, syy * (1.0f / 32.0f));
        sK[r][lane] = (y - muk) * rsqrtf(vk + 1e-5f) * (K_SCALE * klen[c * 32 + r]);
    }
    __syncthreads();

    // ---- Phase 1c: partial matrices for this (chunk, head) ----
    {
        int grp = tid >> 6, t = tid & 63;
        float* outp = &g_part[bx * MATS];
        if (grp < 3) {
            // C[a][b] = sum_r X[r][a] * Y[r][b]
            const float (*X)[36] = (grp == 0) ? sK : (grp == 1) ? sQ : sK;
            const float (*Y)[36] = (grp == 0) ? sK : (grp == 1) ? sQ : sV;
            int a0 = (t & 7) * 4, b0 = (t >> 3) * 4;
            float acc[4][4] = {};
            #pragma unroll 4
            for (int r = 0; r < 32; r++) {
                float4 xa = *(const float4*)&X[r][a0];
                float4 yb = *(const float4*)&Y[r][b0];
                float xs[4] = {xa.x, xa.y, xa.z, xa.w};
                float ys[4] = {yb.x, yb.y, yb.z, yb.w};
                #pragma unroll
                for (int i = 0; i < 4; i++)
                    #pragma unroll
                    for (int j = 0; j < 4; j++)
                        acc[i][j] = fmaf(xs[i], ys[j], acc[i][j]);
            }
            int base = grp * 1024;
            #pragma unroll
            for (int i = 0; i < 4; i++)
                #pragma unroll
                for (int j = 0; j < 4; j++)
                    outp[base + (a0 + i) * 32 + (b0 + j)] = acc[i][j];
        } else if (t < 32) {
            float s = 0.0f;
            #pragma unroll
            for (int r = 0; r < 32; r++) s += sK[r][t];
            outp[3072 + t] = s;
        }
    }

    grid_barrier();

    // ---- Reduce: sum 16 chunk-partials per head (one elem / thread) ----
    {
        int t = bx * 256 + tid;
        if (t < H * MATS) {
            int hh = t / MATS, o = t - hh * MATS;
            float s = 0.0f;
            #pragma unroll
            for (int cc = 0; cc < NCHUNK; cc++)
                s += g_part[(cc * 8 + hh) * MATS + o];
            g_mats[t] = s;
        }
    }

    grid_barrier();

    // ---- Phase 2a: stage this head's matrices ----
    {
        const float* m = &g_mats[h * MATS];
        for (int i = tid; i < 1024; i += 256) {
            int r = i >> 5, col = i & 31;
            sKK[r][col] = m[i];
            sQQ[r][col] = m[1024 + i];
            sKV[r][col] = m[2048 + i];
        }
        if (tid < 32) sKs[tid] = m[3072 + tid];
    }
    __syncthreads();

    // ---- Phase 2b: epilogue for this block's own 32 rows (4 rows / warp) ----
    {
        int r0 = w * 4;
        float o1[4] = {}, wq[4] = {}, wk[4] = {};
        #pragma unroll
        for (int d = 0; d < 32; d++) {
            float a = sKV[d][lane];     // strided, conflict-free
            float b = sKK[d][lane];
            float cc2 = sQQ[d][lane];
            #pragma unroll
            for (int r = 0; r < 4; r++) {
                float qd = sQ[r0 + r][d];   // broadcast LDS
                float kd = sK[r0 + r][d];   // broadcast LDS
                o1[r] = fmaf(qd, a,   o1[r]);
                wq[r] = fmaf(qd, b,   wq[r]);
                wk[r] = fmaf(kd, cc2, wk[r]);
            }
        }
        #pragma unroll
        for (int r = 0; r < 4; r++) {
            int rr = r0 + r;
            float qm = sQ[rr][lane], km = sK[rr][lane], vm = sV[rr][lane];
            float tn = fmaf(0.5f * wq[r], qm, qm * sKs[lane]); // norm partial
            float tc = wk[r] * km;                             // k^T SQQ k partial
            #pragma unroll
            for (int o = 16; o; o >>= 1) {
                tn += __shfl_xor_sync(FULL, tn, o);
                tc += __shfl_xor_sync(FULL, tc, o);
            }
            int l = c * 32 + rr;
            out[(l * H + h) * 32 + lane] = (o1[r] + 0.5f * tc * vm) / tn;
        }
    }
}

extern "C" void kernel_launch(void* const* d_in, const int* in_sizes, int n_in,
                              void* d_out, int out_size) {
    const float* q    = (const float*)d_in[0];
    const float* k    = (const float*)d_in[1];
    const float* v    = (const float*)d_in[2];
    // d_in[3] attn_mask, d_in[4] query_lengths: unused by the reference
    const float* klen = (const float*)d_in[5];
    float* out = (float*)d_out;

    fused_kernel<<<NBLOCKS, 256>>>(q, k, v, klen, out);
}

// round 4
// speedup vs baseline: 1.0019x; 1.0019x over previous
#include <cuda_runtime.h>

#define FULL 0xFFFFFFFFu

// Problem shape (fixed): N=1, L=S=512, H=8, D=M=32
constexpr int L = 512;
constexpr int H = 8;
constexpr int ROWS = 16;              // rows per chunk
constexpr int NCHUNK = 32;            // 32 chunks x 16 rows
constexpr int NBLOCKS = NCHUNK * H;   // 256 blocks, 2 CTAs/SM -> co-resident
constexpr int MATS = 3 * 1024 + 32;   // KK(1024) SQQ(1024) KV(1024) Ksum(32)
constexpr float K_SCALE = 0.05892556509887896f; // 1/(3*sqrt(32))

__device__ float g_part[NBLOCKS * MATS];
__device__ float g_mats[H * MATS];
__device__ unsigned g_cnt = 0;
__device__ unsigned g_gen = 0;

__device__ __forceinline__ unsigned ld_acq(const unsigned* p) {
    unsigned v;
    asm volatile("ld.acquire.gpu.u32 %0, [%1];" : "=r"(v) : "l"(p) : "memory");
    return v;
}
__device__ __forceinline__ void red_add_rel(unsigned* p, unsigned v) {
    asm volatile("red.release.gpu.add.u32 [%0], %1;" :: "l"(p), "r"(v) : "memory");
}
__device__ __forceinline__ unsigned atom_add_acqrel(unsigned* p, unsigned v) {
    unsigned old;
    asm volatile("atom.acq_rel.gpu.add.u32 %0, [%1], %2;"
                 : "=r"(old) : "l"(p), "r"(v) : "memory");
    return old;
}

// Software grid barrier (sense-reversal), tight spin (NO nanosleep).
// Safe: all 256 CTAs co-resident (occ>=2 at this footprint), wave-1.
__device__ __forceinline__ void grid_barrier() {
    __syncthreads();
    if (threadIdx.x == 0) {
        unsigned my = ld_acq(&g_gen);
        if (atom_add_acqrel(&g_cnt, 1u) == NBLOCKS - 1) {
            g_cnt = 0;                 // ordered before gen bump by release
            red_add_rel(&g_gen, 1u);
        } else {
            while (ld_acq(&g_gen) == my) { }
        }
    }
    __syncthreads();
}

__global__ __launch_bounds__(256) void fused_kernel(
        const float* __restrict__ q, const float* __restrict__ k,
        const float* __restrict__ v, const float* __restrict__ klen,
        float* __restrict__ out) {
    __shared__ __align__(16) float sQ[ROWS][36];
    __shared__ __align__(16) float sK[ROWS][36];
    __shared__ __align__(16) float sV[ROWS][36];
    __shared__ float sKK[32][33];
    __shared__ float sQQ[32][33];
    __shared__ float sKV[32][33];   // KV[d][m] = sum_s K[s][d] V[s][m]
    __shared__ float sKs[32];

    int bx = blockIdx.x;
    int h = bx & 7, c = bx >> 3;          // head, 16-row chunk
    int tid = threadIdx.x, lane = tid & 31, w = tid >> 5;

    // ---- Phase 1a: load raw tiles (coalesced, 512 floats each) ----
    for (int i = tid; i < ROWS * 32; i += 256) {
        int r = i >> 5, col = i & 31;
        int g = ((c * ROWS + r) * H + h) * 32 + col;
        sQ[r][col] = q[g];
        sK[r][col] = k[g];
        sV[r][col] = v[g];
    }
    __syncthreads();

    // ---- Phase 1b: LayerNorm (warp w -> rows w, w+8) ----
    #pragma unroll
    for (int rr = 0; rr < 2; rr++) {
        int r = w + rr * 8;
        float x = sQ[r][lane], y = sK[r][lane];
        float sx = x, sxx = x * x, sy = y, syy = y * y;
        #pragma unroll
        for (int o = 16; o; o >>= 1) {
            sx  += __shfl_xor_sync(FULL, sx,  o);
            sxx += __shfl_xor_sync(FULL, sxx, o);
            sy  += __shfl_xor_sync(FULL, sy,  o);
            syy += __shfl_xor_sync(FULL, syy, o);
        }
        float muq = sx * (1.0f / 32.0f);
        float vq  = fmaf(-muq, muq, sxx * (1.0f / 32.0f));
        sQ[r][lane] = (x - muq) * rsqrtf(vq + 1e-5f);
        float muk = sy * (1.0f / 32.0f);
        float vk  = fmaf(-muk, muk, syy * (1.0f / 32.0f));
        sK[r][lane] = (y - muk) * rsqrtf(vk + 1e-5f) * (K_SCALE * klen[c * ROWS + r]);
    }
    __syncthreads();

    // ---- Phase 1c: partial matrices (balanced across all 8 warps) ----
    // KK: warps 0-1 (4x4 tiles), SQQ: warps 2-3 (4x4), KV: warps 4-7 (4x2).
    {
        float* outp = &g_part[bx * MATS];
        if (tid < 128) {
            // C[a][b] = sum_r X[r][a] * X[r][b], 4x4 tile per thread
            int t = tid & 63;
            const float (*X)[36] = (tid < 64) ? sK : sQ;
            int a0 = (t & 7) * 4, b0 = (t >> 3) * 4;
            float acc[4][4] = {};
            #pragma unroll 4
            for (int r = 0; r < ROWS; r++) {
                float4 xa = *(const float4*)&X[r][a0];
                float4 yb = *(const float4*)&X[r][b0];
                float xs[4] = {xa.x, xa.y, xa.z, xa.w};
                float ys[4] = {yb.x, yb.y, yb.z, yb.w};
                #pragma unroll
                for (int i = 0; i < 4; i++)
                    #pragma unroll
                    for (int j = 0; j < 4; j++)
                        acc[i][j] = fmaf(xs[i], ys[j], acc[i][j]);
            }
            int base = (tid < 64) ? 0 : 1024;
            #pragma unroll
            for (int i = 0; i < 4; i++)
                *(float4*)&outp[base + (a0 + i) * 32 + b0] =
                    make_float4(acc[i][0], acc[i][1], acc[i][2], acc[i][3]);
        } else {
            // KV[d][m] = sum_r K[r][d] V[r][m], 4x2 tile per thread (128 thr)
            int t = tid - 128;
            int a0 = (t & 7) * 4, b0 = (t >> 3) * 2;
            float acc[4][2] = {};
            #pragma unroll 4
            for (int r = 0; r < ROWS; r++) {
                float4 xa = *(const float4*)&sK[r][a0];
                float2 yb = *(const float2*)&sV[r][b0];
                float xs[4] = {xa.x, xa.y, xa.z, xa.w};
                #pragma unroll
                for (int i = 0; i < 4; i++) {
                    acc[i][0] = fmaf(xs[i], yb.x, acc[i][0]);
                    acc[i][1] = fmaf(xs[i], yb.y, acc[i][1]);
                }
            }
            #pragma unroll
            for (int i = 0; i < 4; i++)
                *(float2*)&outp[2048 + (a0 + i) * 32 + b0] =
                    make_float2(acc[i][0], acc[i][1]);
            // Ksum on warp 4 (t < 32) after its KV tile
            if (t < 32) {
                float s = 0.0f;
                #pragma unroll
                for (int r = 0; r < ROWS; r++) s += sK[r][t];
                outp[3072 + t] = s;
            }
        }
    }

    grid_barrier();

    // ---- Reduce: sum 32 chunk-partials per head (one elem / thread) ----
    {
        int t = bx * 256 + tid;
        if (t < H * MATS) {
            int hh = t / MATS, o = t - hh * MATS;
            float s = 0.0f;
            #pragma unroll
            for (int cc = 0; cc < NCHUNK; cc++)
                s += g_part[(cc * 8 + hh) * MATS + o];
            g_mats[t] = s;
        }
    }

    grid_barrier();

    // ---- Phase 2a: stage this head's matrices ----
    {
        const float* m = &g_mats[h * MATS];
        for (int i = tid; i < 1024; i += 256) {
            int r = i >> 5, col = i & 31;
            sKK[r][col] = m[i];
            sQQ[r][col] = m[1024 + i];
            sKV[r][col] = m[2048 + i];
        }
        if (tid < 32) sKs[tid] = m[3072 + tid];
    }
    __syncthreads();

    // ---- Phase 2b: epilogue for this block's 16 rows (2 rows / warp) ----
    {
        int r0 = w * 2;
        float o1[2] = {}, wq[2] = {}, wk[2] = {};
        #pragma unroll
        for (int d = 0; d < 32; d++) {
            float a = sKV[d][lane];     // strided, conflict-free
            float b = sKK[d][lane];
            float cc2 = sQQ[d][lane];
            #pragma unroll
            for (int r = 0; r < 2; r++) {
                float qd = sQ[r0 + r][d];   // broadcast LDS
                float kd = sK[r0 + r][d];   // broadcast LDS
                o1[r] = fmaf(qd, a,   o1[r]);
                wq[r] = fmaf(qd, b,   wq[r]);
                wk[r] = fmaf(kd, cc2, wk[r]);
            }
        }
        #pragma unroll
        for (int r = 0; r < 2; r++) {
            int rr = r0 + r;
            float qm = sQ[rr][lane], km = sK[rr][lane], vm = sV[rr][lane];
            float tn = fmaf(0.5f * wq[r], qm, qm * sKs[lane]); // norm partial
            float tc = wk[r] * km;                             // k^T SQQ k partial
            #pragma unroll
            for (int o = 16; o; o >>= 1) {
                tn += __shfl_xor_sync(FULL, tn, o);
                tc += __shfl_xor_sync(FULL, tc, o);
            }
            int l = c * ROWS + rr;
            out[(l * H + h) * 32 + lane] = (o1[r] + 0.5f * tc * vm) / tn;
        }
    }
}

extern "C" void kernel_launch(void* const* d_in, const int* in_sizes, int n_in,
                              void* d_out, int out_size) {
    const float* q    = (const float*)d_in[0];
    const float* k    = (const float*)d_in[1];
    const float* v    = (const float*)d_in[2];
    // d_in[3] attn_mask, d_in[4] query_lengths: unused by the reference
    const float* klen = (const float*)d_in[5];
    float* out = (float*)d_out;

    fused_kernel<<<NBLOCKS, 256>>>(q, k, v, klen, out);
}

// round 6
// speedup vs baseline: 1.1380x; 1.1359x over previous
#include <cuda_runtime.h>

#define FULL 0xFFFFFFFFu

// Problem shape (fixed): N=1, L=S=512, H=8, D=M=32
constexpr int H = 8;
constexpr int ROWS = 32;              // rows per chunk
constexpr int NCHUNK = 16;            // chunks per head
constexpr int NBLOCKS = NCHUNK * H;   // 128 CTAs, all wave-1 co-resident
constexpr int MATS = 3 * 1024 + 32;   // KK(1024) SQQ(1024) KV(1024) Ksum(32)
constexpr int SLICE = MATS / NCHUNK;  // 194 (exact: 194*16 = 3104)
constexpr float K_SCALE = 0.05892556509887896f; // 1/(3*sqrt(32))

static_assert(SLICE * NCHUNK == MATS, "slice must tile MATS");

__device__ float g_part[NBLOCKS * MATS];
__device__ float g_mats[H * MATS];
// Per-head monotonic epoch counters, padded 256B apart to dodge L2-slice pairing.
__device__ unsigned g_c1[H * 64];
__device__ unsigned g_c2[H * 64];

__device__ __forceinline__ unsigned ld_acq(const unsigned* p) {
    unsigned v;
    asm volatile("ld.acquire.gpu.u32 %0, [%1];" : "=r"(v) : "l"(p) : "memory");
    return v;
}
__device__ __forceinline__ unsigned atom_add_acqrel(unsigned* p, unsigned v) {
    unsigned old;
    asm volatile("atom.acq_rel.gpu.add.u32 %0, [%1], %2;"
                 : "=r"(old) : "l"(p), "r"(v) : "memory");
    return old;
}

// Per-head barrier: 16 CTAs of one head rendezvous on a monotonic counter.
// Epoch derived from own arrival value -> no resets, replay-safe (graph
// replays are stream-serialized so epochs cannot interleave).
__device__ __forceinline__ void head_barrier(unsigned* ctr) {
    __syncthreads();                       // all CTA writes done before release
    if (threadIdx.x == 0) {
        unsigned old = atom_add_acqrel(ctr, 1u);
        unsigned target = (old / NCHUNK) * NCHUNK + NCHUNK;
        while ((int)(ld_acq(ctr) - target) < 0) { }
    }
    __syncthreads();                       // propagate acquire CTA-wide
}

__global__ __launch_bounds__(256) void fused_kernel(
        const float* __restrict__ q, const float* __restrict__ k,
        const float* __restrict__ v, const float* __restrict__ klen,
        float* __restrict__ out) {
    __shared__ __align__(16) float sQ[ROWS][36];
    __shared__ __align__(16) float sK[ROWS][36];
    __shared__ __align__(16) float sV[ROWS][36];
    __shared__ float sKK[32][33];
    __shared__ float sQQ[32][33];
    __shared__ float sKV[32][33];   // KV[d][m] = sum_s K[s][d] V[s][m]
    __shared__ float sKs[32];

    int bx = blockIdx.x;
    int h = bx & 7, c = bx >> 3;          // head, 32-row chunk
    int tid = threadIdx.x, lane = tid & 31, w = tid >> 5;

    // ---- Phase 1a: load raw tiles (coalesced) ----
    for (int i = tid; i < ROWS * 32; i += 256) {
        int r = i >> 5, col = i & 31;
        int g = ((c * ROWS + r) * H + h) * 32 + col;
        sQ[r][col] = q[g];
        sK[r][col] = k[g];
        sV[r][col] = v[g];
    }
    __syncthreads();

    // ---- Phase 1b: LayerNorm (warp w -> rows w, w+8, w+16, w+24) ----
    #pragma unroll
    for (int rr = 0; rr < 4; rr++) {
        int r = w + rr * 8;
        float x = sQ[r][lane], y = sK[r][lane];
        float sx = x, sxx = x * x, sy = y, syy = y * y;
        #pragma unroll
        for (int o = 16; o; o >>= 1) {
            sx  += __shfl_xor_sync(FULL, sx,  o);
            sxx += __shfl_xor_sync(FULL, sxx, o);
            sy  += __shfl_xor_sync(FULL, sy,  o);
            syy += __shfl_xor_sync(FULL, syy, o);
        }
        float muq = sx * (1.0f / 32.0f);
        float vq  = fmaf(-muq, muq, sxx * (1.0f / 32.0f));
        sQ[r][lane] = (x - muq) * rsqrtf(vq + 1e-5f);
        float muk = sy * (1.0f / 32.0f);
        float vk  = fmaf(-muk, muk, syy * (1.0f / 32.0f));
        sK[r][lane] = (y - muk) * rsqrtf(vk + 1e-5f) * (K_SCALE * klen[c * ROWS + r]);
    }
    __syncthreads();

    // ---- Phase 1c: partial matrices (KK: w0-1, SQQ: w2-3, KV: w4-7) ----
    {
        float* outp = &g_part[bx * MATS];
        if (tid < 128) {
            int t = tid & 63;
            const float (*X)[36] = (tid < 64) ? sK : sQ;
            int a0 = (t & 7) * 4, b0 = (t >> 3) * 4;
            float acc[4][4] = {};
            #pragma unroll 4
            for (int r = 0; r < ROWS; r++) {
                float4 xa = *(const float4*)&X[r][a0];
                float4 yb = *(const float4*)&X[r][b0];
                float xs[4] = {xa.x, xa.y, xa.z, xa.w};
                float ys[4] = {yb.x, yb.y, yb.z, yb.w};
                #pragma unroll
                for (int i = 0; i < 4; i++)
                    #pragma unroll
                    for (int j = 0; j < 4; j++)
                        acc[i][j] = fmaf(xs[i], ys[j], acc[i][j]);
            }
            int base = (tid < 64) ? 0 : 1024;
            #pragma unroll
            for (int i = 0; i < 4; i++)
                *(float4*)&outp[base + (a0 + i) * 32 + b0] =
                    make_float4(acc[i][0], acc[i][1], acc[i][2], acc[i][3]);
        } else {
            // KV[d][m] = sum_r K[r][d] V[r][m], 4x2 tile per thread
            int t = tid - 128;
            int a0 = (t & 7) * 4, b0 = (t >> 3) * 2;
            float acc[4][2] = {};
            #pragma unroll 4
            for (int r = 0; r < ROWS; r++) {
                float4 xa = *(const float4*)&sK[r][a0];
                float2 yb = *(const float2*)&sV[r][b0];
                float xs[4] = {xa.x, xa.y, xa.z, xa.w};
                #pragma unroll
                for (int i = 0; i < 4; i++) {
                    acc[i][0] = fmaf(xs[i], yb.x, acc[i][0]);
                    acc[i][1] = fmaf(xs[i], yb.y, acc[i][1]);
                }
            }
            #pragma unroll
            for (int i = 0; i < 4; i++)
                *(float2*)&outp[2048 + (a0 + i) * 32 + b0] =
                    make_float2(acc[i][0], acc[i][1]);
            if (t < 32) {
                float s = 0.0f;
                #pragma unroll
                for (int r = 0; r < ROWS; r++) s += sK[r][t];
                outp[3072 + t] = s;
            }
        }
    }

    head_barrier(&g_c1[h * 64]);   // all 16 partials of head h visible

    // ---- Reduce: this CTA sums its 194-element slice over 16 chunks ----
    if (tid < SLICE) {
        int o = c * SLICE + tid;               // coalesced across threads
        float s = 0.0f;
        #pragma unroll
        for (int cc = 0; cc < NCHUNK; cc++)
            s += g_part[(cc * 8 + h) * MATS + o];
        g_mats[h * MATS + o] = s;
    }

    head_barrier(&g_c2[h * 64]);   // full g_mats[h] visible

    // ---- Phase 2a: stage this head's matrices ----
    {
        const float* m = &g_mats[h * MATS];
        for (int i = tid; i < 1024; i += 256) {
            int r = i >> 5, col = i & 31;
            sKK[r][col] = m[i];
            sQQ[r][col] = m[1024 + i];
            sKV[r][col] = m[2048 + i];
        }
        if (tid < 32) sKs[tid] = m[3072 + tid];
    }
    __syncthreads();

    // ---- Phase 2b: epilogue for this block's 32 rows (4 rows / warp) ----
    {
        int r0 = w * 4;
        float o1[4] = {}, wq[4] = {}, wk[4] = {};
        #pragma unroll
        for (int d = 0; d < 32; d++) {
            float a = sKV[d][lane];     // strided, conflict-free
            float b = sKK[d][lane];
            float cc2 = sQQ[d][lane];
            #pragma unroll
            for (int r = 0; r < 4; r++) {
                float qd = sQ[r0 + r][d];   // broadcast LDS
                float kd = sK[r0 + r][d];   // broadcast LDS
                o1[r] = fmaf(qd, a,   o1[r]);
                wq[r] = fmaf(qd, b,   wq[r]);
                wk[r] = fmaf(kd, cc2, wk[r]);
            }
        }
        #pragma unroll
        for (int r = 0; r < 4; r++) {
            int rr = r0 + r;
            float qm = sQ[rr][lane], km = sK[rr][lane], vm = sV[rr][lane];
            float tn = fmaf(0.5f * wq[r], qm, qm * sKs[lane]); // norm partial
            float tc = wk[r] * km;                             // k^T SQQ k partial
            #pragma unroll
            for (int o = 16; o; o >>= 1) {
                tn += __shfl_xor_sync(FULL, tn, o);
                tc += __shfl_xor_sync(FULL, tc, o);
            }
            int l = c * ROWS + rr;
            out[(l * H + h) * 32 + lane] = (o1[r] + 0.5f * tc * vm) / tn;
        }
    }
}

extern "C" void kernel_launch(void* const* d_in, const int* in_sizes, int n_in,
                              void* d_out, int out_size) {
    const float* q    = (const float*)d_in[0];
    const float* k    = (const float*)d_in[1];
    const float* v    = (const float*)d_in[2];
    // d_in[3] attn_mask, d_in[4] query_lengths: unused by the reference
    const float* klen = (const float*)d_in[5];
    float* out = (float*)d_out;

    fused_kernel<<<NBLOCKS, 256>>>(q, k, v, klen, out);
}